// round 11
// baseline (speedup 1.0000x reference)
#include <cuda_runtime.h>
#include <math.h>
#include <stdint.h>

#define BB 256     // batch
#define TT 512     // time steps
#define DIN 128    // input dim
#define HH 256     // hidden
#define G4 1024    // 4*H
#define OUTF 128   // final out features
#define BHH (BB * HH)

#define NB_CTAS 128
#define NGROUPS 8        // batch-tile groups (32 rows each)
#define GROUP_CTAS 16
#define WPAD 260
#define RPAD 68

// SMEM layout (floats)
#define OFF_WS0 0
#define OFF_WS1 (64 * WPAD)
#define OFF_HS0 (128 * WPAD)
#define OFF_HS1 (160 * WPAD)
#define OFF_RS0 (192 * WPAD)
#define OFF_RS1 (OFF_RS0 + 32 * RPAD)
#define FUSED_FLOATS (OFF_RS1 + 32 * RPAD)   // 54,272 floats = 217,088 B

typedef unsigned long long ull;

// ---------------- scratch (device globals; no allocations allowed) ----------
__device__ float g_XP[(size_t)TT * BB * G4];    // layer-0 x_proj [T,B,4H]
__device__ float g_H0[2 * BHH];                 // layer-0 h ping-pong
__device__ float g_H1[2 * BHH];                 // layer-1 h ping-pong
__device__ float g_HLAST[BHH];                  // final h1
__device__ unsigned g_flag0[NGROUPS * GROUP_CTAS * 32];  // layer-0 arrival flags
__device__ unsigned g_flag1[NGROUPS * GROUP_CTAS * 32];  // layer-1 arrival flags

// ---------------- helpers ----------------------------------------------------
__device__ __forceinline__ void ffma2(ull& d, ull a, ull b) {
    asm("fma.rn.f32x2 %0, %1, %2, %0;" : "+l"(d) : "l"(a), "l"(b));
}
__device__ __forceinline__ float red2(ull v) {
    float lo = __uint_as_float((unsigned)(v & 0xffffffffu));
    float hi = __uint_as_float((unsigned)(v >> 32));
    return lo + hi;
}
__device__ __forceinline__ float fsig(float x) {
    return __fdividef(1.f, 1.f + __expf(-x));
}
__device__ __forceinline__ float ftanh(float x) {
    return 2.f * __fdividef(1.f, 1.f + __expf(-2.f * x)) - 1.f;
}

// ---------------- init: zero h buffers and flags ------------------------------
__global__ void init_kernel() {
    int i = blockIdx.x * blockDim.x + threadIdx.x;
    if (i < 2 * BHH) { g_H0[i] = 0.f; g_H1[i] = 0.f; }
    if (i < NGROUPS * GROUP_CTAS * 32) { g_flag0[i] = 0u; g_flag1[i] = 0u; }
}

// ---------------- generic GEMM + bias (f32x2) -- validated ---------------------
template <int K>
__global__ void gemm_bias_kernel(const float* __restrict__ A,
                                 size_t rowStrideB, size_t strideT,
                                 const float* __restrict__ W,
                                 const float* __restrict__ b1,
                                 const float* __restrict__ b2,
                                 float* __restrict__ outp, int ldOut)
{
    __shared__ __align__(16) float As[64][68];
    __shared__ __align__(16) float Ws[64][68];

    const int t   = blockIdx.z;
    const int bb  = blockIdx.y * 64;
    const int nn  = blockIdx.x * 64;
    const int tid = threadIdx.x;
    const int r0  = tid & 15;
    const int c0  = tid >> 4;

    ull acc2[4][4];
#pragma unroll
    for (int m = 0; m < 4; m++)
#pragma unroll
        for (int n = 0; n < 4; n++) acc2[m][n] = 0ull;

    const float* Abase = A + (size_t)bb * rowStrideB + (size_t)t * strideT;
    const float* Wbase = W + (size_t)nn * K;

    for (int kt = 0; kt < K; kt += 64) {
#pragma unroll
        for (int i = 0; i < 4; i++) {
            int lin = i * 256 + tid;
            int row = lin >> 4;
            int c4  = (lin & 15) * 4;
            *(float4*)&As[row][c4] =
                *(const float4*)(Abase + (size_t)row * rowStrideB + kt + c4);
            *(float4*)&Ws[row][c4] =
                *(const float4*)(Wbase + (size_t)row * K + kt + c4);
        }
        __syncthreads();

#pragma unroll
        for (int k = 0; k < 64; k += 4) {
            ulonglong2 a2[4], w2[4];
#pragma unroll
            for (int m = 0; m < 4; m++) a2[m] = *(ulonglong2*)&As[r0 + 16 * m][k];
#pragma unroll
            for (int n = 0; n < 4; n++) w2[n] = *(ulonglong2*)&Ws[c0 + 16 * n][k];
#pragma unroll
            for (int m = 0; m < 4; m++)
#pragma unroll
                for (int n = 0; n < 4; n++) {
                    ffma2(acc2[m][n], a2[m].x, w2[n].x);
                    ffma2(acc2[m][n], a2[m].y, w2[n].y);
                }
        }
        __syncthreads();
    }

#pragma unroll
    for (int m = 0; m < 4; m++)
#pragma unroll
        for (int n = 0; n < 4; n++) {
            int row = bb + r0 + 16 * m;
            int col = nn + c0 + 16 * n;
            float bias = (b1 != nullptr) ? (b1[col] + b2[col]) : 0.f;
            outp[((size_t)t * BB + row) * ldOut + col] = red2(acc2[m][n]) + bias;
        }
}

// ---------------- fused 2-layer persistent LSTM, decoupled layer rings ---------
// 128 CTAs x 256 threads. CTA (jt,bt): hidden slice jj..jj+15, batch bb..bb+31.
// Iteration u: layer0 makes h0(u) (u<TT), releases flag0 mid-iteration; layer1
// makes h1(u-1) from h1(u-2) + h0(u-1) (u>=1), releases flag1 at end. The ih
// GEMM (needs only h0(u-1)) runs before the flag1 wait -> overlap.
__global__ void __launch_bounds__(256, 1)
lstm_fused_kernel(const float* __restrict__ xp,     // [T,B,4H] layer-0 x_proj
                  const float* __restrict__ Whh0,   // [4H,H]
                  const float* __restrict__ Whh1,   // [4H,H]
                  const float* __restrict__ Wih1,   // [4H,H]
                  const float* __restrict__ bih1,
                  const float* __restrict__ bhh1,
                  float* __restrict__ h0buf,        // [2][B,H]
                  float* __restrict__ h1buf,        // [2][B,H]
                  float* __restrict__ hlast)        // [B,H]
{
    extern __shared__ __align__(16) float smg[];
    float* Ws0 = smg + OFF_WS0;   // [64][WPAD]
    float* Ws1 = smg + OFF_WS1;   // [64][WPAD]
    float* Hs0 = smg + OFF_HS0;   // [32][WPAD]
    float* Hs1 = smg + OFF_HS1;   // [32][WPAD]
    float* Rs0 = smg + OFF_RS0;   // [32][RPAD]
    float* Rs1 = smg + OFF_RS1;   // [32][RPAD]

    const int tid = threadIdx.x;
    const int jt  = blockIdx.x & 15;
    const int bt  = blockIdx.x >> 4;
    const int jj  = jt * 16;
    const int bb  = bt * 32;
    const int kg  = tid >> 7;        // warpgroup: k half
    const int lt  = tid & 127;
    const int jl  = lt >> 3;         // 0..15 hidden unit within tile
    const int br  = lt & 7;          // batch rows br,br+8,br+16,br+24
    const int j   = jj + jl;
    const int kb  = kg * 128;        // k base for this warpgroup
    const float* wih_t = Wih1 + (size_t)j * HH + kb;
    const int selfflag = (bt * GROUP_CTAS + jt) * 32;

    // ---- load both W_hh slices: smem row = g*16 + jloc
#pragma unroll
    for (int i = 0; i < 16; i++) {
        int lin  = i * 256 + tid;
        int srow = lin >> 6;
        int c4   = (lin & 63) * 4;
        int g    = srow >> 4;
        int jloc = srow & 15;
        size_t grow = (size_t)(g * HH + jj + jloc) * HH + c4;
        *(float4*)&Ws0[srow * WPAD + c4] = *(const float4*)(Whh0 + grow);
        *(float4*)&Ws1[srow * WPAD + c4] = *(const float4*)(Whh1 + grow);
    }

    float cacc0[4] = {0.f, 0.f, 0.f, 0.f};
    float cacc1[4] = {0.f, 0.f, 0.f, 0.f};
    float bias1[4];
    float xv_cur[4][4], xv_nxt[4][4];
    if (kg == 0) {
#pragma unroll
        for (int g = 0; g < 4; g++)
            bias1[g] = bih1[g * HH + j] + bhh1[g * HH + j];
#pragma unroll
        for (int m = 0; m < 4; m++) {
            const float* xr = xp + (size_t)(bb + br + 8 * m) * G4;
#pragma unroll
            for (int g = 0; g < 4; g++) xv_cur[m][g] = __ldg(xr + g * HH + j);
        }
    }
    __syncthreads();   // W slices ready

    for (int u = 0; u <= TT; u++) {
        // ======== layer-0 ring: wait peers' h0(u-1), stage Hs0 ========
        if (u > 0) {
            if (tid < GROUP_CTAS) {
                volatile unsigned* f = &g_flag0[(bt * GROUP_CTAS + tid) * 32];
                while (*f < (unsigned)u) {}
                __threadfence();
            }
            __syncthreads();
        }
        {
            const float* hin0 = h0buf + (size_t)((u + 1) & 1) * BHH;
#pragma unroll
            for (int i = 0; i < 8; i++) {
                int lin = i * 256 + tid;
                int row = lin >> 6;
                int c4  = (lin & 63) * 4;
                *(float4*)&Hs0[row * WPAD + c4] =
                    __ldcg((const float4*)(hin0 + (size_t)(bb + row) * HH + c4));
            }
        }
        __syncthreads();

        if (kg == 0 && u + 1 < TT) {
            const float* xpt = xp + (size_t)(u + 1) * BB * G4;
#pragma unroll
            for (int m = 0; m < 4; m++) {
                const float* xr = xpt + (size_t)(bb + br + 8 * m) * G4;
#pragma unroll
                for (int g = 0; g < 4; g++) xv_nxt[m][g] = __ldg(xr + g * HH + j);
            }
        }

        // ======== layer-0 GEMM + early flag0 release ========
        if (u < TT) {
            ull acc0[4][4];
#pragma unroll
            for (int m = 0; m < 4; m++)
#pragma unroll
                for (int g = 0; g < 4; g++) acc0[m][g] = 0ull;

#pragma unroll 4
            for (int k = kb; k < kb + 128; k += 4) {
                ulonglong2 h2[4], w2[4];
#pragma unroll
                for (int m = 0; m < 4; m++)
                    h2[m] = *(ulonglong2*)&Hs0[(br + 8 * m) * WPAD + k];
#pragma unroll
                for (int g = 0; g < 4; g++)
                    w2[g] = *(ulonglong2*)&Ws0[(g * 16 + jl) * WPAD + k];
#pragma unroll
                for (int m = 0; m < 4; m++)
#pragma unroll
                    for (int g = 0; g < 4; g++) {
                        ffma2(acc0[m][g], h2[m].x, w2[g].x);
                        ffma2(acc0[m][g], h2[m].y, w2[g].y);
                    }
            }

            if (kg == 1) {
#pragma unroll
                for (int m = 0; m < 4; m++)
#pragma unroll
                    for (int g = 0; g < 4; g++)
                        Rs0[(8 * m + br) * RPAD + g * 16 + jl] = red2(acc0[m][g]);
            }
            __syncthreads();

            if (kg == 0) {
                float* hout = h0buf + (size_t)(u & 1) * BHH;
#pragma unroll
                for (int m = 0; m < 4; m++) {
                    int b = bb + br + 8 * m;
                    const float* rrow = &Rs0[(8 * m + br) * RPAD];
                    float vi = red2(acc0[m][0]) + rrow[0 * 16 + jl] + xv_cur[m][0];
                    float vf = red2(acc0[m][1]) + rrow[1 * 16 + jl] + xv_cur[m][1];
                    float vg = red2(acc0[m][2]) + rrow[2 * 16 + jl] + xv_cur[m][2];
                    float vo = red2(acc0[m][3]) + rrow[3 * 16 + jl] + xv_cur[m][3];

                    float ig = fsig(vi), fg = fsig(vf), gg = ftanh(vg), og = fsig(vo);
                    float cn = fg * cacc0[m] + ig * gg;
                    cacc0[m] = cn;
                    __stcg(hout + (size_t)b * HH + j, og * ftanh(cn));
#pragma unroll
                    for (int g = 0; g < 4; g++) xv_cur[m][g] = xv_nxt[m][g];
                }
                // kg0-only barrier: all h0 stores issued, then release flag0
                asm volatile("bar.sync 1, 128;" ::: "memory");
                if (tid == 0) {
                    __threadfence();
                    *(volatile unsigned*)&g_flag0[selfflag] = (unsigned)(u + 1);
                }
            }
            // kg1 continues into layer-1 ih immediately (no join here)
        }

        // ======== layer 1: ih GEMM first (only needs Hs0), then hh ========
        if (u >= 1) {
            ull acc1[4][4];
#pragma unroll
            for (int m = 0; m < 4; m++)
#pragma unroll
                for (int g = 0; g < 4; g++) acc1[m][g] = 0ull;

            // 2-stage register pipeline on W_ih1 (L2-resident)
            ulonglong2 wb[2][4];
#pragma unroll
            for (int p = 0; p < 2; p++)
#pragma unroll
                for (int g = 0; g < 4; g++)
                    wb[p][g] = __ldg((const ulonglong2*)
                                     (wih_t + (size_t)g * HH * HH + p * 4));

#pragma unroll
            for (int it = 0; it < 32; it += 2) {
                ulonglong2 cur[2][4];
#pragma unroll
                for (int p = 0; p < 2; p++)
#pragma unroll
                    for (int g = 0; g < 4; g++) cur[p][g] = wb[p][g];
                if (it + 2 < 32) {
#pragma unroll
                    for (int p = 0; p < 2; p++)
#pragma unroll
                        for (int g = 0; g < 4; g++)
                            wb[p][g] = __ldg((const ulonglong2*)
                                (wih_t + (size_t)g * HH * HH + (it + 2 + p) * 4));
                }
#pragma unroll
                for (int p = 0; p < 2; p++) {
                    int k = kb + (it + p) * 4;
                    ulonglong2 h2[4];
#pragma unroll
                    for (int m = 0; m < 4; m++)
                        h2[m] = *(ulonglong2*)&Hs0[(br + 8 * m) * WPAD + k];
#pragma unroll
                    for (int m = 0; m < 4; m++)
#pragma unroll
                        for (int g = 0; g < 4; g++) {
                            ffma2(acc1[m][g], h2[m].x, cur[p][g].x);
                            ffma2(acc1[m][g], h2[m].y, cur[p][g].y);
                        }
                }
            }

            // ---- wait peers' h1(u-2) (released a full iteration ago) ----
            if (tid < GROUP_CTAS) {
                volatile unsigned* f = &g_flag1[(bt * GROUP_CTAS + tid) * 32];
                while (*f < (unsigned)u) {}
                __threadfence();
            }
            __syncthreads();

            {
                const float* hin1 = h1buf + (size_t)(u & 1) * BHH;
#pragma unroll
                for (int i = 0; i < 8; i++) {
                    int lin = i * 256 + tid;
                    int row = lin >> 6;
                    int c4  = (lin & 63) * 4;
                    *(float4*)&Hs1[row * WPAD + c4] =
                        __ldcg((const float4*)(hin1 + (size_t)(bb + row) * HH + c4));
                }
            }
            __syncthreads();

            // ---- hh GEMM (SMEM-resident W_hh1)
#pragma unroll 4
            for (int k = kb; k < kb + 128; k += 4) {
                ulonglong2 h2[4], w2[4];
#pragma unroll
                for (int m = 0; m < 4; m++)
                    h2[m] = *(ulonglong2*)&Hs1[(br + 8 * m) * WPAD + k];
#pragma unroll
                for (int g = 0; g < 4; g++)
                    w2[g] = *(ulonglong2*)&Ws1[(g * 16 + jl) * WPAD + k];
#pragma unroll
                for (int m = 0; m < 4; m++)
#pragma unroll
                    for (int g = 0; g < 4; g++) {
                        ffma2(acc1[m][g], h2[m].x, w2[g].x);
                        ffma2(acc1[m][g], h2[m].y, w2[g].y);
                    }
            }

            if (kg == 1) {
#pragma unroll
                for (int m = 0; m < 4; m++)
#pragma unroll
                    for (int g = 0; g < 4; g++)
                        Rs1[(8 * m + br) * RPAD + g * 16 + jl] = red2(acc1[m][g]);
            }
            __syncthreads();

            if (kg == 0) {
                float* hout = h1buf + (size_t)((u - 1) & 1) * BHH;
#pragma unroll
                for (int m = 0; m < 4; m++) {
                    int b = bb + br + 8 * m;
                    const float* rrow = &Rs1[(8 * m + br) * RPAD];
                    float vi = red2(acc1[m][0]) + rrow[0 * 16 + jl] + bias1[0];
                    float vf = red2(acc1[m][1]) + rrow[1 * 16 + jl] + bias1[1];
                    float vg = red2(acc1[m][2]) + rrow[2 * 16 + jl] + bias1[2];
                    float vo = red2(acc1[m][3]) + rrow[3 * 16 + jl] + bias1[3];

                    float ig = fsig(vi), fg = fsig(vf), gg = ftanh(vg), og = fsig(vo);
                    float cn = fg * cacc1[m] + ig * gg;
                    cacc1[m] = cn;
                    float hn = og * ftanh(cn);
                    __stcg(hout + (size_t)b * HH + j, hn);
                    if (u == TT) hlast[(size_t)b * HH + j] = hn;
                }
                asm volatile("bar.sync 1, 128;" ::: "memory");
                if (tid == 0) {
                    __threadfence();
                    *(volatile unsigned*)&g_flag1[selfflag] = (unsigned)(u + 1);
                }
            }
        } else {
            // u == 0: bootstrap flag1 (h1 buffers are init-zeroed)
            if (tid == 0) {
                __threadfence();
                *(volatile unsigned*)&g_flag1[selfflag] = 1u;
            }
        }
    }
}

// ---------------- launcher ---------------------------------------------------
extern "C" void kernel_launch(void* const* d_in, const int* in_sizes, int n_in,
                              void* d_out, int out_size)
{
    const float* x     = (const float*)d_in[0];
    const float* W_ih0 = (const float*)d_in[1];
    const float* W_hh0 = (const float*)d_in[2];
    const float* b_ih0 = (const float*)d_in[3];
    const float* b_hh0 = (const float*)d_in[4];
    const float* W_ih1 = (const float*)d_in[5];
    const float* W_hh1 = (const float*)d_in[6];
    const float* b_ih1 = (const float*)d_in[7];
    const float* b_hh1 = (const float*)d_in[8];
    const float* W_fc  = (const float*)d_in[9];
    float* outp = (float*)d_out;
    (void)in_sizes; (void)n_in; (void)out_size;

    float *XP, *H0, *H1, *HLAST;
    cudaGetSymbolAddress((void**)&XP,    g_XP);
    cudaGetSymbolAddress((void**)&H0,    g_H0);
    cudaGetSymbolAddress((void**)&H1,    g_H1);
    cudaGetSymbolAddress((void**)&HLAST, g_HLAST);

    static bool attr_set = false;
    if (!attr_set) {
        cudaFuncSetAttribute(lstm_fused_kernel,
                             cudaFuncAttributeMaxDynamicSharedMemorySize,
                             FUSED_FLOATS * (int)sizeof(float));
        attr_set = true;
    }
    const size_t fsmemB = FUSED_FLOATS * sizeof(float);

    init_kernel<<<(2 * BHH + 255) / 256, 256>>>();
    gemm_bias_kernel<DIN><<<dim3(16, 4, TT), 256>>>(
        x, (size_t)TT * DIN, (size_t)DIN, W_ih0, b_ih0, b_hh0, XP, G4);
    lstm_fused_kernel<<<NB_CTAS, 256, fsmemB>>>(
        XP, W_hh0, W_hh1, W_ih1, b_ih1, b_hh1, H0, H1, HLAST);

    // ---------- final FC: out = h1_last @ W_fc^T ----------
    gemm_bias_kernel<HH><<<dim3(2, 4, 1), 256>>>(
        HLAST, (size_t)HH, 0, W_fc, nullptr, nullptr, outp, OUTF);
}

// round 14
// speedup vs baseline: 1.0176x; 1.0176x over previous
#include <cuda_runtime.h>
#include <math.h>
#include <stdint.h>

#define BB 256     // batch
#define TT 512     // time steps
#define DIN 128    // input dim
#define HH 256     // hidden
#define G4 1024    // 4*H
#define OUTF 128   // final out features
#define BHH (BB * HH)

#define NB_CTAS 128
#define NGROUPS 8        // batch-tile groups (32 rows each)
#define GROUP_CTAS 16
#define WPAD 260
#define XPAD 132
#define RPAD 68

// SMEM layout (floats)
#define OFF_WS0 0                              // Whh0 [64][WPAD]
#define OFF_WI0 (OFF_WS0 + 64 * WPAD)          // Wih0 [64][XPAD]
#define OFF_HS0 (OFF_WI0 + 64 * XPAD)          // h0 tile [32][WPAD]
#define OFF_HS1 (OFF_HS0 + 32 * WPAD)          // h1 tile [32][WPAD]
#define OFF_XS  (OFF_HS1 + 32 * WPAD)          // x tile  [32][XPAD]
#define OFF_RS0 (OFF_XS + 32 * XPAD)           // partials L0 [32][RPAD]
#define OFF_RS1 (OFF_RS0 + 32 * RPAD)          // partials L1 [32][RPAD]
#define FUSED_FLOATS (OFF_RS1 + 32 * RPAD)     // 50,304 floats = 201,216 B

typedef unsigned long long ull;

// ---------------- scratch (device globals; no allocations allowed) ----------
__device__ float g_H0[2 * BHH];                 // layer-0 h ping-pong
__device__ float g_H1[2 * BHH];                 // layer-1 h ping-pong
__device__ float g_HLAST[BHH];                  // final h1
__device__ unsigned g_flag[NGROUPS * GROUP_CTAS * 32];  // per-CTA flags, 128B apart

// ---------------- helpers ----------------------------------------------------
__device__ __forceinline__ void ffma2(ull& d, ull a, ull b) {
    asm("fma.rn.f32x2 %0, %1, %2, %0;" : "+l"(d) : "l"(a), "l"(b));
}
__device__ __forceinline__ float red2(ull v) {
    float lo = __uint_as_float((unsigned)(v & 0xffffffffu));
    float hi = __uint_as_float((unsigned)(v >> 32));
    return lo + hi;
}
__device__ __forceinline__ float fsig(float x) {
    return __fdividef(1.f, 1.f + __expf(-x));
}
__device__ __forceinline__ float ftanh(float x) {
    return 2.f * __fdividef(1.f, 1.f + __expf(-2.f * x)) - 1.f;
}
__device__ __forceinline__ void cp_async16(uint32_t dst, const void* src) {
    asm volatile("cp.async.ca.shared.global [%0], [%1], 16;" :: "r"(dst), "l"(src));
}

// ---------------- init: zero h buffers and flags ------------------------------
__global__ void init_kernel() {
    int i = blockIdx.x * blockDim.x + threadIdx.x;
    if (i < 2 * BHH) { g_H0[i] = 0.f; g_H1[i] = 0.f; }
    if (i < NGROUPS * GROUP_CTAS * 32) g_flag[i] = 0u;
}

// ---------------- generic GEMM + bias (f32x2) -- used for final FC ------------
template <int K>
__global__ void gemm_bias_kernel(const float* __restrict__ A,
                                 size_t rowStrideB, size_t strideT,
                                 const float* __restrict__ W,
                                 const float* __restrict__ b1,
                                 const float* __restrict__ b2,
                                 float* __restrict__ outp, int ldOut)
{
    __shared__ __align__(16) float As[64][68];
    __shared__ __align__(16) float Ws[64][68];

    const int t   = blockIdx.z;
    const int bb  = blockIdx.y * 64;
    const int nn  = blockIdx.x * 64;
    const int tid = threadIdx.x;
    const int r0  = tid & 15;
    const int c0  = tid >> 4;

    ull acc2[4][4];
#pragma unroll
    for (int m = 0; m < 4; m++)
#pragma unroll
        for (int n = 0; n < 4; n++) acc2[m][n] = 0ull;

    const float* Abase = A + (size_t)bb * rowStrideB + (size_t)t * strideT;
    const float* Wbase = W + (size_t)nn * K;

    for (int kt = 0; kt < K; kt += 64) {
#pragma unroll
        for (int i = 0; i < 4; i++) {
            int lin = i * 256 + tid;
            int row = lin >> 4;
            int c4  = (lin & 15) * 4;
            *(float4*)&As[row][c4] =
                *(const float4*)(Abase + (size_t)row * rowStrideB + kt + c4);
            *(float4*)&Ws[row][c4] =
                *(const float4*)(Wbase + (size_t)row * K + kt + c4);
        }
        __syncthreads();

#pragma unroll
        for (int k = 0; k < 64; k += 4) {
            ulonglong2 a2[4], w2[4];
#pragma unroll
            for (int m = 0; m < 4; m++) a2[m] = *(ulonglong2*)&As[r0 + 16 * m][k];
#pragma unroll
            for (int n = 0; n < 4; n++) w2[n] = *(ulonglong2*)&Ws[c0 + 16 * n][k];
#pragma unroll
            for (int m = 0; m < 4; m++)
#pragma unroll
                for (int n = 0; n < 4; n++) {
                    ffma2(acc2[m][n], a2[m].x, w2[n].x);
                    ffma2(acc2[m][n], a2[m].y, w2[n].y);
                }
        }
        __syncthreads();
    }

#pragma unroll
    for (int m = 0; m < 4; m++)
#pragma unroll
        for (int n = 0; n < 4; n++) {
            int row = bb + r0 + 16 * m;
            int col = nn + c0 + 16 * n;
            float bias = (b1 != nullptr) ? (b1[col] + b2[col]) : 0.f;
            outp[((size_t)t * BB + row) * ldOut + col] = red2(acc2[m][n]) + bias;
        }
}

// ---------------- fully-fused 2-layer persistent LSTM --------------------------
// 128 CTAs x 256 threads. CTA (jt,bt): hidden slice jj..jj+15, batch bb..bb+31.
// Iteration u: layer0 computes h0(u) = f(h0(u-1), x(u)) with the input
// projection folded in as k-columns 256..383 (Wih0 SMEM-resident, x tile
// cp.async-prefetched); layer1 computes h1(u-1) from h1(u-2) and h0(u-1)
// with BOTH its weight matrices streamed from L2 (kg0: Whh1 x Hs1,
// kg1: Wih1 x Hs0). One flag per iteration.
__global__ void __launch_bounds__(256, 1)
lstm_fused_kernel(const float* __restrict__ x,      // [B,T,DIN]
                  const float* __restrict__ Whh0,   // [4H,H]
                  const float* __restrict__ Wih0,   // [4H,DIN]
                  const float* __restrict__ bih0,
                  const float* __restrict__ bhh0,
                  const float* __restrict__ Whh1,   // [4H,H]
                  const float* __restrict__ Wih1,   // [4H,H]
                  const float* __restrict__ bih1,
                  const float* __restrict__ bhh1,
                  float* __restrict__ h0buf,        // [2][B,H]
                  float* __restrict__ h1buf,        // [2][B,H]
                  float* __restrict__ hlast)        // [B,H]
{
    extern __shared__ __align__(16) float smg[];
    float* Ws0 = smg + OFF_WS0;   // [64][WPAD]
    float* Wi0 = smg + OFF_WI0;   // [64][XPAD]
    float* Hs0 = smg + OFF_HS0;   // [32][WPAD]
    float* Hs1 = smg + OFF_HS1;   // [32][WPAD]
    float* Xs  = smg + OFF_XS;    // [32][XPAD]
    float* Rs0 = smg + OFF_RS0;   // [32][RPAD]
    float* Rs1 = smg + OFF_RS1;   // [32][RPAD]

    const int tid = threadIdx.x;
    const int jt  = blockIdx.x & 15;
    const int bt  = blockIdx.x >> 4;
    const int jj  = jt * 16;
    const int bb  = bt * 32;
    const int kg  = tid >> 7;        // warpgroup
    const int lt  = tid & 127;
    const int jl  = lt >> 3;         // 0..15 hidden unit within tile
    const int br  = lt & 7;          // batch rows br,br+8,br+16,br+24
    const int j   = jj + jl;
    const int selfflag = (bt * GROUP_CTAS + jt) * 32;
    // layer-1 streamed weight base: kg0 -> Whh1 (vs Hs1), kg1 -> Wih1 (vs Hs0)
    const float* w1base = ((kg == 0) ? Whh1 : Wih1) + (size_t)j * HH;
    const uint32_t xs_u32 = (uint32_t)__cvta_generic_to_shared(Xs);

    // ---- load Whh0 + Wih0 slices (SMEM-resident): smem row = g*16 + jloc
#pragma unroll
    for (int i = 0; i < 16; i++) {
        int lin  = i * 256 + tid;       // 0..4095 float4 units
        int srow = lin >> 6;            // 0..63
        int c4   = (lin & 63) * 4;
        int g    = srow >> 4;
        int jloc = srow & 15;
        *(float4*)&Ws0[srow * WPAD + c4] =
            *(const float4*)(Whh0 + (size_t)(g * HH + jj + jloc) * HH + c4);
    }
#pragma unroll
    for (int i = 0; i < 8; i++) {
        int lin  = i * 256 + tid;       // 0..2047 float4 units
        int srow = lin >> 5;            // 0..63
        int c4   = (lin & 31) * 4;
        int g    = srow >> 4;
        int jloc = srow & 15;
        *(float4*)&Wi0[srow * XPAD + c4] =
            *(const float4*)(Wih0 + (size_t)(g * HH + jj + jloc) * DIN + c4);
    }
    // ---- kg1 kicks off x(0) prefetch
    if (kg == 1) {
#pragma unroll
        for (int i = 0; i < 8; i++) {
            int lin = i * 128 + lt;     // 0..1023 float4 units
            int row = lin >> 5;         // 0..31
            int c4  = (lin & 31) * 4;
            cp_async16(xs_u32 + (uint32_t)((row * XPAD + c4) * 4),
                       x + ((size_t)(bb + row) * TT + 0) * DIN + c4);
        }
        asm volatile("cp.async.commit_group;" ::: "memory");
    }

    float cacc0[4] = {0.f, 0.f, 0.f, 0.f};
    float cacc1[4] = {0.f, 0.f, 0.f, 0.f};
    float bias0[4], bias1[4];
    if (kg == 0) {
#pragma unroll
        for (int g = 0; g < 4; g++) {
            bias0[g] = bih0[g * HH + j] + bhh0[g * HH + j];
            bias1[g] = bih1[g * HH + j] + bhh1[g * HH + j];
        }
    }
    __syncthreads();   // W slices ready

    for (int u = 0; u <= TT; u++) {
        // ---- wait for all group CTAs to have finished iteration u-1
        if (u > 0) {
            if (tid < GROUP_CTAS) {
                volatile unsigned* f = &g_flag[(bt * GROUP_CTAS + tid) * 32];
                while (*f < (unsigned)u) {}
                __threadfence();
            }
            __syncthreads();
        }

        // ---- stage h0(u-1) and h1(u-2); ensure x(u) landed
        {
            const float* hin0 = h0buf + (size_t)((u + 1) & 1) * BHH;
            const float* hin1 = h1buf + (size_t)(u & 1) * BHH;
#pragma unroll
            for (int i = 0; i < 8; i++) {
                int lin = i * 256 + tid;
                int row = lin >> 6;
                int c4  = (lin & 63) * 4;
                size_t goff = (size_t)(bb + row) * HH + c4;
                *(float4*)&Hs0[row * WPAD + c4] = __ldcg((const float4*)(hin0 + goff));
                *(float4*)&Hs1[row * WPAD + c4] = __ldcg((const float4*)(hin1 + goff));
            }
        }
        asm volatile("cp.async.wait_all;" ::: "memory");
        __syncthreads();

        // ======== layer 0 GEMM over concatenated k: [Hs0 | Xs] ========
        ull acc0[4][4];
#pragma unroll
        for (int m = 0; m < 4; m++)
#pragma unroll
            for (int g = 0; g < 4; g++) acc0[m][g] = 0ull;

        if (u < TT) {
            if (kg == 0) {
                // k = 0..191 (h part)
#pragma unroll 4
                for (int k = 0; k < 192; k += 4) {
                    ulonglong2 h2[4], w2[4];
#pragma unroll
                    for (int m = 0; m < 4; m++)
                        h2[m] = *(ulonglong2*)&Hs0[(br + 8 * m) * WPAD + k];
#pragma unroll
                    for (int g = 0; g < 4; g++)
                        w2[g] = *(ulonglong2*)&Ws0[(g * 16 + jl) * WPAD + k];
#pragma unroll
                    for (int m = 0; m < 4; m++)
#pragma unroll
                        for (int g = 0; g < 4; g++) {
                            ffma2(acc0[m][g], h2[m].x, w2[g].x);
                            ffma2(acc0[m][g], h2[m].y, w2[g].y);
                        }
                }
            } else {
                // k = 192..255 (h part)
#pragma unroll 4
                for (int k = 192; k < 256; k += 4) {
                    ulonglong2 h2[4], w2[4];
#pragma unroll
                    for (int m = 0; m < 4; m++)
                        h2[m] = *(ulonglong2*)&Hs0[(br + 8 * m) * WPAD + k];
#pragma unroll
                    for (int g = 0; g < 4; g++)
                        w2[g] = *(ulonglong2*)&Ws0[(g * 16 + jl) * WPAD + k];
#pragma unroll
                    for (int m = 0; m < 4; m++)
#pragma unroll
                        for (int g = 0; g < 4; g++) {
                            ffma2(acc0[m][g], h2[m].x, w2[g].x);
                            ffma2(acc0[m][g], h2[m].y, w2[g].y);
                        }
                }
                // k = 0..127 of x part
#pragma unroll 4
                for (int k = 0; k < 128; k += 4) {
                    ulonglong2 h2[4], w2[4];
#pragma unroll
                    for (int m = 0; m < 4; m++)
                        h2[m] = *(ulonglong2*)&Xs[(br + 8 * m) * XPAD + k];
#pragma unroll
                    for (int g = 0; g < 4; g++)
                        w2[g] = *(ulonglong2*)&Wi0[(g * 16 + jl) * XPAD + k];
#pragma unroll
                    for (int m = 0; m < 4; m++)
#pragma unroll
                        for (int g = 0; g < 4; g++) {
                            ffma2(acc0[m][g], h2[m].x, w2[g].x);
                            ffma2(acc0[m][g], h2[m].y, w2[g].y);
                        }
                }
            }
        }

        // ======== layer 1 GEMM: kg0 = Hs1 x Whh1, kg1 = Hs0 x Wih1 ========
        ull acc1[4][4];
#pragma unroll
        for (int m = 0; m < 4; m++)
#pragma unroll
            for (int g = 0; g < 4; g++) acc1[m][g] = 0ull;

        if (u >= 1) {
            const float* Asm = (kg == 0) ? Hs1 : Hs0;
            // 2-stage register pipeline on streamed W (L2-resident)
            ulonglong2 wb[2][4];
#pragma unroll
            for (int p = 0; p < 2; p++)
#pragma unroll
                for (int g = 0; g < 4; g++)
                    wb[p][g] = __ldg((const ulonglong2*)
                                     (w1base + (size_t)g * HH * HH + p * 4));

#pragma unroll
            for (int it = 0; it < 64; it += 2) {
                ulonglong2 cur[2][4];
#pragma unroll
                for (int p = 0; p < 2; p++)
#pragma unroll
                    for (int g = 0; g < 4; g++) cur[p][g] = wb[p][g];
                if (it + 2 < 64) {
#pragma unroll
                    for (int p = 0; p < 2; p++)
#pragma unroll
                        for (int g = 0; g < 4; g++)
                            wb[p][g] = __ldg((const ulonglong2*)
                                (w1base + (size_t)g * HH * HH + (it + 2 + p) * 4));
                }
#pragma unroll
                for (int p = 0; p < 2; p++) {
                    int k = (it + p) * 4;
                    ulonglong2 h2[4];
#pragma unroll
                    for (int m = 0; m < 4; m++)
                        h2[m] = *(ulonglong2*)&Asm[(br + 8 * m) * WPAD + k];
#pragma unroll
                    for (int m = 0; m < 4; m++)
#pragma unroll
                        for (int g = 0; g < 4; g++) {
                            ffma2(acc1[m][g], h2[m].x, cur[p][g].x);
                            ffma2(acc1[m][g], h2[m].y, cur[p][g].y);
                        }
                }
            }
        }

        // ======== single publish phase: kg1 -> Rs0, Rs1 ========
        if (kg == 1) {
            if (u < TT) {
#pragma unroll
                for (int m = 0; m < 4; m++)
#pragma unroll
                    for (int g = 0; g < 4; g++)
                        Rs0[(8 * m + br) * RPAD + g * 16 + jl] = red2(acc0[m][g]);
            }
            if (u >= 1) {
#pragma unroll
                for (int m = 0; m < 4; m++)
#pragma unroll
                    for (int g = 0; g < 4; g++)
                        Rs1[(8 * m + br) * RPAD + g * 16 + jl] = red2(acc1[m][g]);
            }
        }
        __syncthreads();

        // ======== kg0: both epilogues; kg1: prefetch x(u+1) ========
        if (kg == 0) {
            if (u < TT) {
                float* hout = h0buf + (size_t)(u & 1) * BHH;
#pragma unroll
                for (int m = 0; m < 4; m++) {
                    int b = bb + br + 8 * m;
                    const float* rrow = &Rs0[(8 * m + br) * RPAD];
                    float vi = red2(acc0[m][0]) + rrow[0 * 16 + jl] + bias0[0];
                    float vf = red2(acc0[m][1]) + rrow[1 * 16 + jl] + bias0[1];
                    float vg = red2(acc0[m][2]) + rrow[2 * 16 + jl] + bias0[2];
                    float vo = red2(acc0[m][3]) + rrow[3 * 16 + jl] + bias0[3];

                    float ig = fsig(vi), fg = fsig(vf), gg = ftanh(vg), og = fsig(vo);
                    float cn = fg * cacc0[m] + ig * gg;
                    cacc0[m] = cn;
                    __stcg(hout + (size_t)b * HH + j, og * ftanh(cn));
                }
            }
            if (u >= 1) {
                float* hout = h1buf + (size_t)((u - 1) & 1) * BHH;
#pragma unroll
                for (int m = 0; m < 4; m++) {
                    int b = bb + br + 8 * m;
                    const float* rrow = &Rs1[(8 * m + br) * RPAD];
                    float vi = red2(acc1[m][0]) + rrow[0 * 16 + jl] + bias1[0];
                    float vf = red2(acc1[m][1]) + rrow[1 * 16 + jl] + bias1[1];
                    float vg = red2(acc1[m][2]) + rrow[2 * 16 + jl] + bias1[2];
                    float vo = red2(acc1[m][3]) + rrow[3 * 16 + jl] + bias1[3];

                    float ig = fsig(vi), fg = fsig(vf), gg = ftanh(vg), og = fsig(vo);
                    float cn = fg * cacc1[m] + ig * gg;
                    cacc1[m] = cn;
                    float hn = og * ftanh(cn);
                    __stcg(hout + (size_t)b * HH + j, hn);
                    if (u == TT) hlast[(size_t)b * HH + j] = hn;
                }
            }
        } else {
            // prefetch x(u+1) into Xs (safe: Xs(u) consumed before publish sync)
            if (u + 1 < TT) {
#pragma unroll
                for (int i = 0; i < 8; i++) {
                    int lin = i * 128 + lt;
                    int row = lin >> 5;
                    int c4  = (lin & 31) * 4;
                    cp_async16(xs_u32 + (uint32_t)((row * XPAD + c4) * 4),
                               x + ((size_t)(bb + row) * TT + (u + 1)) * DIN + c4);
                }
                asm volatile("cp.async.commit_group;" ::: "memory");
            }
        }

        // ---- arrive
        __syncthreads();
        if (tid == 0) {
            __threadfence();
            *(volatile unsigned*)&g_flag[selfflag] = (unsigned)(u + 1);
        }
    }
}

// ---------------- launcher ---------------------------------------------------
extern "C" void kernel_launch(void* const* d_in, const int* in_sizes, int n_in,
                              void* d_out, int out_size)
{
    const float* x     = (const float*)d_in[0];
    const float* W_ih0 = (const float*)d_in[1];
    const float* W_hh0 = (const float*)d_in[2];
    const float* b_ih0 = (const float*)d_in[3];
    const float* b_hh0 = (const float*)d_in[4];
    const float* W_ih1 = (const float*)d_in[5];
    const float* W_hh1 = (const float*)d_in[6];
    const float* b_ih1 = (const float*)d_in[7];
    const float* b_hh1 = (const float*)d_in[8];
    const float* W_fc  = (const float*)d_in[9];
    float* outp = (float*)d_out;
    (void)in_sizes; (void)n_in; (void)out_size;

    float *H0, *H1, *HLAST;
    cudaGetSymbolAddress((void**)&H0,    g_H0);
    cudaGetSymbolAddress((void**)&H1,    g_H1);
    cudaGetSymbolAddress((void**)&HLAST, g_HLAST);

    static bool attr_set = false;
    if (!attr_set) {
        cudaFuncSetAttribute(lstm_fused_kernel,
                             cudaFuncAttributeMaxDynamicSharedMemorySize,
                             FUSED_FLOATS * (int)sizeof(float));
        attr_set = true;
    }
    const size_t fsmemB = FUSED_FLOATS * sizeof(float);

    init_kernel<<<(2 * BHH + 255) / 256, 256>>>();
    lstm_fused_kernel<<<NB_CTAS, 256, fsmemB>>>(
        x, W_hh0, W_ih0, b_ih0, b_hh0, W_hh1, W_ih1, b_ih1, b_hh1,
        H0, H1, HLAST);

    // ---------- final FC: out = h1_last @ W_fc^T ----------
    gemm_bias_kernel<HH><<<dim3(2, 4, 1), 256>>>(
        HLAST, (size_t)HH, 0, W_fc, nullptr, nullptr, outp, OUTF);
}